// round 2
// baseline (speedup 1.0000x reference)
#include <cuda_runtime.h>

// Problem constants
#define NNODES 1024
#define BB     8
#define FF     128
#define OO     128
#define DDIR   3
#define NB     (NNODES*BB)      // 8192

// ---------------- scratch (static device memory; no allocations) ----------------
__device__ float g_support[DDIR*NNODES*BB*OO];   // [d][n][b][o]
__device__ float g_agg    [DDIR*NNODES*BB*OO];   // [d][n][b][o] (rows contiguous, 128 wide)
__device__ float g_gi     [DDIR*NNODES*BB*384];  // rows follow agg rows, 384 wide
__device__ float g_ght    [NB*512];              // [n*B+b][ gh_r|gh_z|gh_n|t_pre ]
__device__ float g_x      [NB*FF];               // intermediate x after layer 0
__device__ float g_wihT   [2*128*384];           // Wih^T per layer
__device__ float g_wcat   [2*128*512];           // [Whh^T | Wh] per layer
__device__ float g_bcat   [2*512];               // [bhh | Bh] per layer

// packed fp32x2 FMA (SASS FFMA2) — 2x fp32 FMA throughput, full precision
__device__ __forceinline__ void ffma2(float2 &c, float a, float bx, float by) {
    asm("{\n\t"
        ".reg .b64 ra, rb, rc;\n\t"
        "mov.b64 ra, {%2, %2};\n\t"
        "mov.b64 rb, {%3, %4};\n\t"
        "mov.b64 rc, {%0, %1};\n\t"
        "fma.rn.f32x2 rc, ra, rb, rc;\n\t"
        "mov.b64 {%0, %1}, rc;\n\t"
        "}" : "+f"(c.x), "+f"(c.y) : "f"(a), "f"(bx), "f"(by));
}

__device__ __forceinline__ float sigmoidf_(float x) {
    return 0.5f * (1.0f + tanhf(0.5f * x));
}

// ---------------------------------------------------------------------------
// Generic strided-batch row-major SGEMM: C[z] = A[z] * B[z] (+ bias), f32x2 core.
//   per-batch bases:
//     baseA = z*aStride
//     baseB = (z/zdiv)*bOuter + (z%zdiv)*bInner
//     baseC = (z/zdiv)*cOuter + (z%zdiv)*cInner
// Dimensions must divide tiles exactly (true for all uses here).
// Thread tile: TM=8 rows x TN=8 cols (two float4 column groups at tx*4 and BN/2+tx*4).
// ---------------------------------------------------------------------------
template<int BM,int BN,int BK,int TM,int NT,int MB>
__global__ void __launch_bounds__(NT, MB) sgemm_k(
    const float* __restrict__ A, const float* __restrict__ Bm,
    const float* __restrict__ bias, float* __restrict__ C,
    int K, int lda, int ldb, int ldc,
    long aStride, long bOuter, long bInner, int zdiv,
    long cOuter, long cInner, int biasStride)
{
    constexpr int TX = BN / 8;           // 16 col groups
    constexpr int LA = BM*BK/(4*NT);     // float4 loads per thread for A tile
    constexpr int LB = BK*BN/(4*NT);     // float4 loads per thread for B tile
    static_assert(BK == 16 && BN == 128, "tile shape fixed");

    const int tid = threadIdx.x;
    const int tx  = tid % TX;
    const int ty  = tid / TX;
    const int z   = blockIdx.z;

    const long baseA = (long)z*aStride + (long)blockIdx.x*BM*lda;
    const long baseB = (long)(z/zdiv)*bOuter + (long)(z%zdiv)*bInner + (long)blockIdx.y*BN;
    const long baseC = (long)(z/zdiv)*cOuter + (long)(z%zdiv)*cInner
                     + (long)blockIdx.x*BM*ldc + (long)blockIdx.y*BN;

    __shared__ __align__(16) float As[2][BK][BM];   // transposed A tile: As[k][m]
    __shared__ __align__(16) float Bs[2][BK][BN];

    float2 acc[TM][4];
    #pragma unroll
    for (int i = 0; i < TM; i++)
        #pragma unroll
        for (int g = 0; g < 4; g++) acc[i][g] = make_float2(0.f, 0.f);

    const int numK = K / BK;

    // -------- preload tile 0 --------
    #pragma unroll
    for (int i = 0; i < LA; i++) {
        int idx = tid + i*NT;
        int row = idx >> 2;
        int kq  = (idx & 3) << 2;
        float4 v = *(const float4*)&A[baseA + (long)row*lda + kq];
        As[0][kq+0][row] = v.x; As[0][kq+1][row] = v.y;
        As[0][kq+2][row] = v.z; As[0][kq+3][row] = v.w;
    }
    #pragma unroll
    for (int i = 0; i < LB; i++) {
        int idx = tid + i*NT;
        int kb  = idx >> 5;
        int jq  = (idx & 31) << 2;
        *(float4*)&Bs[0][kb][jq] = *(const float4*)&Bm[baseB + (long)kb*ldb + jq];
    }
    __syncthreads();

    for (int kt = 0; kt < numK; kt++) {
        const int  cur = kt & 1;
        const bool has = (kt + 1 < numK);
        float4 pa[LA], pb[LB];
        if (has) {
            const int k0 = (kt + 1) * BK;
            #pragma unroll
            for (int i = 0; i < LA; i++) {
                int idx = tid + i*NT;
                int row = idx >> 2;
                int kq  = (idx & 3) << 2;
                pa[i] = *(const float4*)&A[baseA + (long)row*lda + k0 + kq];
            }
            #pragma unroll
            for (int i = 0; i < LB; i++) {
                int idx = tid + i*NT;
                int kb  = idx >> 5;
                int jq  = (idx & 31) << 2;
                pb[i] = *(const float4*)&Bm[baseB + (long)(k0 + kb)*ldb + jq];
            }
        }
        // -------- compute on current buffer --------
        #pragma unroll
        for (int kk = 0; kk < BK; kk++) {
            float4 a0 = *(const float4*)&As[cur][kk][ty*TM];
            float4 a1 = *(const float4*)&As[cur][kk][ty*TM + 4];
            float4 b0 = *(const float4*)&Bs[cur][kk][tx*4];
            float4 b1 = *(const float4*)&Bs[cur][kk][BN/2 + tx*4];
            float av[8] = {a0.x,a0.y,a0.z,a0.w,a1.x,a1.y,a1.z,a1.w};
            #pragma unroll
            for (int i = 0; i < TM; i++) {
                ffma2(acc[i][0], av[i], b0.x, b0.y);
                ffma2(acc[i][1], av[i], b0.z, b0.w);
                ffma2(acc[i][2], av[i], b1.x, b1.y);
                ffma2(acc[i][3], av[i], b1.z, b1.w);
            }
        }
        if (has) {
            const int nxt = cur ^ 1;
            #pragma unroll
            for (int i = 0; i < LA; i++) {
                int idx = tid + i*NT;
                int row = idx >> 2;
                int kq  = (idx & 3) << 2;
                As[nxt][kq+0][row] = pa[i].x; As[nxt][kq+1][row] = pa[i].y;
                As[nxt][kq+2][row] = pa[i].z; As[nxt][kq+3][row] = pa[i].w;
            }
            #pragma unroll
            for (int i = 0; i < LB; i++) {
                int idx = tid + i*NT;
                int kb  = idx >> 5;
                int jq  = (idx & 31) << 2;
                *(float4*)&Bs[nxt][kb][jq] = pb[i];
            }
            __syncthreads();
        }
    }

    // -------- epilogue: bias + store --------
    float4 bv0 = make_float4(0.f,0.f,0.f,0.f), bv1 = bv0;
    if (bias) {
        const float* bp = bias + (long)z*biasStride + (long)blockIdx.y*BN;
        bv0 = *(const float4*)&bp[tx*4];
        bv1 = *(const float4*)&bp[BN/2 + tx*4];
    }
    #pragma unroll
    for (int i = 0; i < TM; i++) {
        float4 v0 = make_float4(acc[i][0].x + bv0.x, acc[i][0].y + bv0.y,
                                acc[i][1].x + bv0.z, acc[i][1].y + bv0.w);
        float4 v1 = make_float4(acc[i][2].x + bv1.x, acc[i][2].y + bv1.y,
                                acc[i][3].x + bv1.z, acc[i][3].y + bv1.w);
        long cr = baseC + (long)(ty*TM + i)*ldc;
        *(float4*)&C[cr + tx*4]          = v0;
        *(float4*)&C[cr + BN/2 + tx*4]   = v1;
    }
}

// ---------------- one-time weight prep: transposes + concat ----------------
__global__ void prep_weights(const float* __restrict__ Wih, const float* __restrict__ Whh,
                             const float* __restrict__ Wh,  const float* __restrict__ bhh,
                             const float* __restrict__ Bh,
                             float* __restrict__ wihT, float* __restrict__ wcat,
                             float* __restrict__ bcat)
{
    int idx = blockIdx.x*blockDim.x + threadIdx.x;   // < 2*128*512 = 131072
    if (idx < 2*128*384) {
        int l = idx / (128*384);
        int rem = idx - l*(128*384);
        int k = rem / 384, j = rem % 384;
        wihT[idx] = Wih[((long)l*384 + j)*128 + k];   // Wih^T
    }
    if (idx < 2*128*512) {
        int l = idx >> 16;
        int rem = idx & 65535;
        int k = rem >> 9, j = rem & 511;
        wcat[idx] = (j < 384) ? Whh[((long)l*384 + j)*128 + k]     // Whh^T
                              : Wh[((long)l*128 + k)*128 + (j-384)]; // Wh
    }
    if (idx < 2*512) {
        int l = idx >> 9, j = idx & 511;
        bcat[idx] = (j < 384) ? bhh[l*384 + j] : Bh[l*128 + (j-384)];
    }
}

// ---------------- fused GRU gates + d-sum + relu + highway ----------------
__global__ void gru_highway(const float* __restrict__ xin, const float* __restrict__ ght,
                            const float* __restrict__ gi, float* __restrict__ xout)
{
    int idx = blockIdx.x*blockDim.x + threadIdx.x;   // < N*B*O = 1048576
    int o = idx & 127;
    int r = idx >> 7;                                // n*B + b
    float h = xin[idx];
    const float* g = ght + (long)r*512;
    float ghr = g[o], ghz = g[128+o], ghn = g[256+o];
    float t = fmaxf(g[384+o], 0.0f);
    float acc = 0.0f;
    #pragma unroll
    for (int d = 0; d < 3; d++) {
        const float* gp = gi + ((long)(d*8192 + r))*384;
        float rr = sigmoidf_(gp[o]       + ghr);
        float zz = sigmoidf_(gp[128 + o] + ghz);
        float nn = tanhf    (gp[256 + o] + rr*ghn);
        acc += (1.0f - zz)*nn + zz*h;
    }
    float outv = fmaxf(acc, 0.0f);
    xout[idx] = outv*t + h*(1.0f - t);
}

// ---------------------------------------------------------------------------
extern "C" void kernel_launch(void* const* d_in, const int* in_sizes, int n_in,
                              void* d_out, int out_size)
{
    const float* inputs = (const float*)d_in[0];
    const float* adj    = (const float*)d_in[1];
    const float* W      = (const float*)d_in[2];
    const float* Bc     = (const float*)d_in[3];
    const float* Wh     = (const float*)d_in[4];
    const float* Bh     = (const float*)d_in[5];
    const float* Wih    = (const float*)d_in[6];
    const float* Whh    = (const float*)d_in[7];
    const float* bih    = (const float*)d_in[8];
    const float* bhh    = (const float*)d_in[9];
    float* out = (float*)d_out;
    (void)in_sizes; (void)n_in; (void)out_size;

    float *support, *agg, *gi, *ght, *xmid, *wihT, *wcat, *bcat;
    cudaGetSymbolAddress((void**)&support, g_support);
    cudaGetSymbolAddress((void**)&agg,     g_agg);
    cudaGetSymbolAddress((void**)&gi,      g_gi);
    cudaGetSymbolAddress((void**)&ght,     g_ght);
    cudaGetSymbolAddress((void**)&xmid,    g_x);
    cudaGetSymbolAddress((void**)&wihT,    g_wihT);
    cudaGetSymbolAddress((void**)&wcat,    g_wcat);
    cudaGetSymbolAddress((void**)&bcat,    g_bcat);

    prep_weights<<<512, 256>>>(Wih, Whh, Wh, bhh, Bh, wihT, wcat, bcat);

    for (int l = 0; l < 2; l++) {
        const float* xi = (l == 0) ? inputs : xmid;
        float*       xo = (l == 1) ? out    : xmid;

        // support[d][n][b][o] = x @ W[l,d] + Bc[l,d]   (batch z = d)
        sgemm_k<128,128,16,8,256,2><<<dim3(64,1,3), 256>>>(
            xi, W + (long)l*3*128*128, Bc + l*3*128, support,
            /*K*/128, /*lda*/128, /*ldb*/128, /*ldc*/128,
            /*aStride*/0L, /*bOuter*/(long)128*128, /*bInner*/0L, /*zdiv*/1,
            /*cOuter*/(long)NNODES*BB*OO, /*cInner*/0L, /*biasStride*/128);

        // agg[d][m][b][o] = adj[d,b] @ support[d][:,b,:]   (batch z = d*8+b)
        sgemm_k<64,128,16,8,128,4><<<dim3(16,1,24), 128>>>(
            adj, support, nullptr, agg,
            /*K*/1024, /*lda*/1024, /*ldb*/1024, /*ldc*/1024,
            /*aStride*/(long)NNODES*NNODES,
            /*bOuter*/(long)NNODES*BB*OO, /*bInner*/128L, /*zdiv*/8,
            /*cOuter*/(long)NNODES*BB*OO, /*cInner*/128L, /*biasStride*/0);

        // gi = agg_flat @ WihT + bih   (M = 24576, N = 384)
        sgemm_k<128,128,16,8,256,2><<<dim3(192,3,1), 256>>>(
            agg, wihT + (long)l*128*384, bih + l*384, gi,
            /*K*/128, /*lda*/128, /*ldb*/384, /*ldc*/384,
            0L, 0L, 0L, 1, 0L, 0L, 0);

        // ght = x @ [Whh^T | Wh] + [bhh | Bh]   (M = 8192, N = 512)
        sgemm_k<128,128,16,8,256,2><<<dim3(64,4,1), 256>>>(
            xi, wcat + (long)l*128*512, bcat + l*512, ght,
            /*K*/128, /*lda*/128, /*ldb*/512, /*ldc*/512,
            0L, 0L, 0L, 1, 0L, 0L, 0);

        // GRU gates + sum over d + relu + highway
        gru_highway<<<4096, 256>>>(xi, ght, gi, xo);
    }
}

// round 7
// speedup vs baseline: 1.6477x; 1.6477x over previous
#include <cuda_runtime.h>
#include <cstdint>

// Problem constants
#define NNODES 1024
#define BB     8
#define FF     128
#define OO     128
#define DDIR   3
#define NB     (NNODES*BB)      // 8192

// ---------------- scratch (static device memory; no allocations) ----------------
__device__ float g_support[DDIR*NNODES*BB*OO];   // [d][n][b][o]
__device__ float g_supT   [DDIR*BB*OO*NNODES];   // [d*8+b][o][n]  (B as [n][k] for mma row.col)
__device__ float g_agg    [DDIR*NNODES*BB*OO];   // [d][n][b][o] (rows contiguous, 128 wide)
__device__ float g_gi     [DDIR*NNODES*BB*384];  // rows follow agg rows, 384 wide
__device__ float g_ght    [NB*512];              // [n*B+b][ gh_r|gh_z|gh_n|t_pre ]
__device__ float g_x      [NB*FF];               // intermediate x after layer 0
__device__ float g_wT     [2*DDIR*OO*FF];        // W[l,d]^T : [l][d][o][f]
__device__ float g_whcat  [2*512*128];           // [l][n][k]: rows 0..383 Whh, 384..511 Wh^T
__device__ float g_bcat   [2*512];               // [bhh | Bh] per layer

// round fp32 -> tf32 (round-to-nearest), kept in fp32 container
__device__ __forceinline__ float tf32r(float x) {
    uint32_t u;
    asm("cvt.rna.tf32.f32 %0, %1;" : "=r"(u) : "f"(x));
    return __uint_as_float(u);
}

__device__ __forceinline__ void mma_tf32(float* c, const uint32_t* a, const uint32_t* b) {
    asm volatile(
        "mma.sync.aligned.m16n8k8.row.col.f32.tf32.tf32.f32 "
        "{%0,%1,%2,%3}, {%4,%5,%6,%7}, {%8,%9}, {%0,%1,%2,%3};"
        : "+f"(c[0]), "+f"(c[1]), "+f"(c[2]), "+f"(c[3])
        : "r"(a[0]), "r"(a[1]), "r"(a[2]), "r"(a[3]), "r"(b[0]), "r"(b[1]));
}

__device__ __forceinline__ float sigmoidf_(float x) {
    return 0.5f * (1.0f + tanhf(0.5f * x));
}

// ---------------------------------------------------------------------------
// Generic tf32 tensor-core GEMM.
//   C[z][m][n] = sum_k A[z][m][k] * B[z][n][k]  (+ bias[n])
//   A row-major [M][K] (lda), B row-major [N][K] (ldb)  (= col-major K x N),
//   C row-major (ldc).
//   baseA = z*aStride + bx*128*lda
//   baseB = z*bStride + by*128*ldb
//   baseC = (z/zdiv)*cOuter + (z%zdiv)*cInner + bx*128*ldc + by*128
// Block 256 thr = 8 warps (2 x 4), warp tile 64x32, BM=BN=128, BK=16.
// ---------------------------------------------------------------------------
__global__ void __launch_bounds__(256, 2) mma_gemm_k(
    const float* __restrict__ A, const float* __restrict__ Bm,
    const float* __restrict__ bias, float* __restrict__ C,
    int K, int lda, int ldb, int ldc,
    long aStride, long bStride, int zdiv,
    long cOuter, long cInner, int biasStride)
{
    const int tid   = threadIdx.x;
    const int warp  = tid >> 5;
    const int lane  = tid & 31;
    const int group = lane >> 2;
    const int tig   = lane & 3;
    const int wm    = (warp >> 2) * 64;
    const int wn    = (warp & 3) * 32;
    const int z     = blockIdx.z;

    const long baseA = (long)z*aStride + (long)blockIdx.x*128*lda;
    const long baseB = (long)z*bStride + (long)blockIdx.y*128*ldb;
    const long baseC = (long)(z/zdiv)*cOuter + (long)(z%zdiv)*cInner
                     + (long)blockIdx.x*128*ldc + (long)blockIdx.y*128;

    __shared__ __align__(16) float As[2][128][20];
    __shared__ __align__(16) float Bs[2][128][20];

    float c[4][4][4];
    #pragma unroll
    for (int ma = 0; ma < 4; ma++)
        #pragma unroll
        for (int na = 0; na < 4; na++)
            #pragma unroll
            for (int q = 0; q < 4; q++) c[ma][na][q] = 0.f;

    const int numK = K / 16;
    const int row  = tid >> 2;          // 0..63 (+64 per i)
    const int kq   = (tid & 3) << 2;    // 0,4,8,12

    // -------- preload tile 0 --------
    #pragma unroll
    for (int i = 0; i < 2; i++) {
        int r = row + i*64;
        float4 va = *(const float4*)&A [baseA + (long)r*lda + kq];
        float4 vb = *(const float4*)&Bm[baseB + (long)r*ldb + kq];
        va.x=tf32r(va.x); va.y=tf32r(va.y); va.z=tf32r(va.z); va.w=tf32r(va.w);
        vb.x=tf32r(vb.x); vb.y=tf32r(vb.y); vb.z=tf32r(vb.z); vb.w=tf32r(vb.w);
        *(float4*)&As[0][r][kq] = va;
        *(float4*)&Bs[0][r][kq] = vb;
    }
    __syncthreads();

    for (int kt = 0; kt < numK; kt++) {
        const int  cur = kt & 1;
        const bool has = (kt + 1 < numK);
        float4 pa[2], pb[2];
        if (has) {
            const int k0 = (kt + 1) * 16;
            #pragma unroll
            for (int i = 0; i < 2; i++) {
                int r = row + i*64;
                pa[i] = *(const float4*)&A [baseA + (long)r*lda + k0 + kq];
                pb[i] = *(const float4*)&Bm[baseB + (long)r*ldb + k0 + kq];
            }
        }
        // -------- compute on current buffer --------
        #pragma unroll
        for (int ks = 0; ks < 16; ks += 8) {
            uint32_t a[4][4], b[4][2];
            #pragma unroll
            for (int ma = 0; ma < 4; ma++) {
                int r0 = wm + ma*16 + group;
                a[ma][0] = __float_as_uint(As[cur][r0    ][ks + tig]);
                a[ma][1] = __float_as_uint(As[cur][r0 + 8][ks + tig]);
                a[ma][2] = __float_as_uint(As[cur][r0    ][ks + tig + 4]);
                a[ma][3] = __float_as_uint(As[cur][r0 + 8][ks + tig + 4]);
            }
            #pragma unroll
            for (int na = 0; na < 4; na++) {
                int n0 = wn + na*8 + group;
                b[na][0] = __float_as_uint(Bs[cur][n0][ks + tig]);
                b[na][1] = __float_as_uint(Bs[cur][n0][ks + tig + 4]);
            }
            #pragma unroll
            for (int ma = 0; ma < 4; ma++)
                #pragma unroll
                for (int na = 0; na < 4; na++)
                    mma_tf32(c[ma][na], a[ma], b[na]);
        }
        if (has) {
            const int nxt = cur ^ 1;
            #pragma unroll
            for (int i = 0; i < 2; i++) {
                int r = row + i*64;
                float4 va = pa[i], vb = pb[i];
                va.x=tf32r(va.x); va.y=tf32r(va.y); va.z=tf32r(va.z); va.w=tf32r(va.w);
                vb.x=tf32r(vb.x); vb.y=tf32r(vb.y); vb.z=tf32r(vb.z); vb.w=tf32r(vb.w);
                *(float4*)&As[nxt][r][kq] = va;
                *(float4*)&Bs[nxt][r][kq] = vb;
            }
            __syncthreads();
        }
    }

    // -------- epilogue: bias + store --------
    const float* bp = bias ? (bias + (long)z*biasStride + blockIdx.y*128) : nullptr;
    #pragma unroll
    for (int ma = 0; ma < 4; ma++) {
        #pragma unroll
        for (int na = 0; na < 4; na++) {
            int gr = wm + ma*16 + group;
            int gc = wn + na*8 + tig*2;
            float b0 = 0.f, b1 = 0.f;
            if (bp) { b0 = bp[gc]; b1 = bp[gc + 1]; }
            long p0 = baseC + (long)gr*ldc + gc;
            float2 v0 = make_float2(c[ma][na][0] + b0, c[ma][na][1] + b1);
            float2 v1 = make_float2(c[ma][na][2] + b0, c[ma][na][3] + b1);
            *(float2*)&C[p0]           = v0;
            *(float2*)&C[p0 + 8*ldc]   = v1;
        }
    }
}

// ---------------- support transpose: [d][n][b][o] -> [db][o][n] ----------------
__global__ void transpose_support(const float* __restrict__ sup, float* __restrict__ supT)
{
    __shared__ float t[32][33];
    int db = blockIdx.z;
    int n0 = blockIdx.x * 32, o0 = blockIdx.y * 32;
    int d = db >> 3, b = db & 7;
    int tx = threadIdx.x, ty = threadIdx.y;   // 32 x 8
    #pragma unroll
    for (int j = 0; j < 4; j++) {
        int n = n0 + ty + j*8;
        t[ty + j*8][tx] = sup[((size_t)(d*1024 + n)*8 + b)*128 + o0 + tx];
    }
    __syncthreads();
    #pragma unroll
    for (int j = 0; j < 4; j++) {
        int o = o0 + ty + j*8;
        supT[((size_t)db*128 + o)*1024 + n0 + tx] = t[tx][ty + j*8];
    }
}

// ---------------- one-time weight prep: transposes + concat ----------------
__global__ void prep_weights(const float* __restrict__ W,   const float* __restrict__ Whh,
                             const float* __restrict__ Wh,  const float* __restrict__ bhh,
                             const float* __restrict__ Bh,
                             float* __restrict__ wT, float* __restrict__ whcat,
                             float* __restrict__ bcat)
{
    int idx = blockIdx.x*blockDim.x + threadIdx.x;   // < 131072
    if (idx < 2*DDIR*128*128) {                      // wT[l][d][o][f] = W[l][d][f][o]
        int ld = idx / 16384;                        // l*3+d
        int rem = idx & 16383;
        int o = rem >> 7, f = rem & 127;
        wT[idx] = W[((long)ld*128 + f)*128 + o];
    }
    if (idx < 2*512*128) {                           // whcat[l][n][k]
        int l = idx >> 16;
        int rem = idx & 65535;
        int n = rem >> 7, k = rem & 127;
        whcat[idx] = (n < 384) ? Whh[((long)l*384 + n)*128 + k]
                               : Wh[((long)l*128 + k)*128 + (n - 384)];
    }
    if (idx < 2*512) {
        int l = idx >> 9, j = idx & 511;
        bcat[idx] = (j < 384) ? bhh[l*384 + j] : Bh[l*128 + (j-384)];
    }
}

// ---------------- fused GRU gates + d-sum + relu + highway ----------------
__global__ void gru_highway(const float* __restrict__ xin, const float* __restrict__ ght,
                            const float* __restrict__ gi, float* __restrict__ xout)
{
    int idx = blockIdx.x*blockDim.x + threadIdx.x;
    int o = idx & 127;
    int r = idx >> 7;
    float h = xin[idx];
    const float* g = ght + (long)r*512;
    float ghr = g[o], ghz = g[128+o], ghn = g[256+o];
    float t = fmaxf(g[384+o], 0.0f);
    float acc = 0.0f;
    #pragma unroll
    for (int d = 0; d < 3; d++) {
        const float* gp = gi + ((long)(d*8192 + r))*384;
        float rr = sigmoidf_(gp[o]       + ghr);
        float zz = sigmoidf_(gp[128 + o] + ghz);
        float nn = tanhf    (gp[256 + o] + rr*ghn);
        acc += (1.0f - zz)*nn + zz*h;
    }
    float outv = fmaxf(acc, 0.0f);
    xout[idx] = outv*t + h*(1.0f - t);
}

// ---------------------------------------------------------------------------
extern "C" void kernel_launch(void* const* d_in, const int* in_sizes, int n_in,
                              void* d_out, int out_size)
{
    const float* inputs = (const float*)d_in[0];
    const float* adj    = (const float*)d_in[1];
    const float* W      = (const float*)d_in[2];
    const float* Bc     = (const float*)d_in[3];
    const float* Wh     = (const float*)d_in[4];
    const float* Bh     = (const float*)d_in[5];
    const float* Wih    = (const float*)d_in[6];
    const float* Whh    = (const float*)d_in[7];
    const float* bih    = (const float*)d_in[8];
    const float* bhh    = (const float*)d_in[9];
    float* out = (float*)d_out;
    (void)in_sizes; (void)n_in; (void)out_size;

    float *support, *supT, *agg, *gi, *ght, *xmid, *wT, *whcat, *bcat;
    cudaGetSymbolAddress((void**)&support, g_support);
    cudaGetSymbolAddress((void**)&supT,    g_supT);
    cudaGetSymbolAddress((void**)&agg,     g_agg);
    cudaGetSymbolAddress((void**)&gi,      g_gi);
    cudaGetSymbolAddress((void**)&ght,     g_ght);
    cudaGetSymbolAddress((void**)&xmid,    g_x);
    cudaGetSymbolAddress((void**)&wT,      g_wT);
    cudaGetSymbolAddress((void**)&whcat,   g_whcat);
    cudaGetSymbolAddress((void**)&bcat,    g_bcat);

    prep_weights<<<512, 256>>>(W, Whh, Wh, bhh, Bh, wT, whcat, bcat);

    for (int l = 0; l < 2; l++) {
        const float* xi = (l == 0) ? inputs : xmid;
        float*       xo = (l == 1) ? out    : xmid;

        // support[d][nb][o] = x @ W[l,d]^T' + Bc[l,d]   (z = d)
        mma_gemm_k<<<dim3(64,1,3), 256>>>(
            xi, wT + (long)l*DDIR*16384, Bc + l*DDIR*128, support,
            128, 128, 128, 128,
            /*aStride*/0L, /*bStride*/16384L, /*zdiv*/1,
            /*cOuter*/(long)NNODES*BB*OO, /*cInner*/0L, /*biasStride*/128);

        // supT[db][o][n] = support[d][:,b,:]^T
        transpose_support<<<dim3(32,4,24), dim3(32,8)>>>(support, supT);

        // agg[d][m][b][o] = adj[d,b] @ support  (z = d*8+b)
        mma_gemm_k<<<dim3(8,1,24), 256>>>(
            adj, supT, nullptr, agg,
            1024, 1024, 1024, 1024,
            /*aStride*/(long)NNODES*NNODES, /*bStride*/131072L, /*zdiv*/8,
            /*cOuter*/(long)NNODES*BB*OO, /*cInner*/128L, /*biasStride*/0);

        // gi = agg_flat @ Wih[l]^T + bih   (Wih natively [384][128] = B[n][k])
        mma_gemm_k<<<dim3(192,3,1), 256>>>(
            agg, Wih + (long)l*384*128, bih + l*384, gi,
            128, 128, 128, 384,
            0L, 0L, 1, 0L, 0L, 0);

        // ght = x @ [Whh | Wh^T]^T + [bhh | Bh]
        mma_gemm_k<<<dim3(64,4,1), 256>>>(
            xi, whcat + (long)l*512*128, bcat + l*512, ght,
            128, 128, 128, 512,
            0L, 0L, 1, 0L, 0L, 0);

        gru_highway<<<4096, 256>>>(xi, ght, gi, xo);
    }
}